// round 13
// baseline (speedup 1.0000x reference)
#include <cuda_runtime.h>
#include <cuda_bf16.h>
#include <math.h>

// ---------------- problem constants ----------------
#define BB   8
#define HSZ  64
#define WSZ  64
#define NSP  (HSZ*WSZ)          // 4096 spatial positions per batch
#define MR   (BB*NSP)           // 32768 rows
#define CC   512
#define TT   77
#define MT   (BB*TT)            // 616 text rows
#define HH8  8
#define DH64 64
#define FFN  2048

// ---------------- scratch (device globals; no runtime alloc) ----------------
__device__ float g_x  [(size_t)MR*CC];   // LN1 output
__device__ float g_q  [(size_t)MR*CC];   // q projection (l2-normed in place)
__device__ float g_kf [(size_t)MT*CC];
__device__ float g_vf [(size_t)MT*CC];
__device__ int   g_pad[MT];
__device__ float g_al [(size_t)MR*CC];   // attention output (pre-wo)
__device__ float g_o  [(size_t)MR*CC];   // aligned@wo + bo
__device__ float g_g  [(size_t)MR*CC];   // gate linear
__device__ float g_cf [(size_t)MR*HH8];  // per-head conf
__device__ float g_y  [(size_t)MR*CC];   // residual stream
__device__ float g_h  [(size_t)MR*CC];   // LN2 output
__device__ float g_f1 [(size_t)MR*FFN];  // ffn intermediate

// ---------------- helpers ----------------
__device__ __forceinline__ float warp_sum(float v){
#pragma unroll
    for (int o = 16; o > 0; o >>= 1) v += __shfl_xor_sync(0xffffffffu, v, o);
    return v;
}
__device__ __forceinline__ float warp_max(float v){
#pragma unroll
    for (int o = 16; o > 0; o >>= 1) v = fmaxf(v, __shfl_xor_sync(0xffffffffu, v, o));
    return v;
}
__device__ __forceinline__ float gelu_exact(float x){
    return 0.5f * x * (1.0f + erff(x * 0.70710678118654752440f));
}

// block of 128 threads: reduce two partial sums to totals (all threads get result)
__device__ __forceinline__ void block_reduce2_128(float& s, float& s2){
    __shared__ float sh[8];
    s  = warp_sum(s);
    s2 = warp_sum(s2);
    int t = threadIdx.x;
    if ((t & 31) == 0){ sh[t >> 5] = s; sh[4 + (t >> 5)] = s2; }
    __syncthreads();
    s  = sh[0] + sh[1] + sh[2] + sh[3];
    s2 = sh[4] + sh[5] + sh[6] + sh[7];
}

// ---------------- LayerNorm over 512 (one block per row, 128 threads) ----------------
__global__ void ln_kernel(const float* __restrict__ in, const float* __restrict__ w,
                          const float* __restrict__ b, float* __restrict__ out){
    int row = blockIdx.x, t = threadIdx.x;
    const float* p = in + (size_t)row * CC;
    float v[4], s = 0.f, s2 = 0.f;
#pragma unroll
    for (int i = 0; i < 4; i++){ float x = p[t + 128*i]; v[i] = x; s += x; s2 += x*x; }
    block_reduce2_128(s, s2);
    float mu  = s  * (1.0f/512.0f);
    float var = s2 * (1.0f/512.0f) - mu*mu;
    float rs  = rsqrtf(var + 1e-5f);
#pragma unroll
    for (int i = 0; i < 4; i++){
        int c = t + 128*i;
        out[(size_t)row*CC + c] = (v[i]-mu)*rs*w[c] + b[c];
    }
}

// ---------------- row-wise L2 normalize (in place) ----------------
__global__ void l2norm_kernel(float* __restrict__ p){
    int row = blockIdx.x, t = threadIdx.x;
    float* r = p + (size_t)row * CC;
    float v[4], s2 = 0.f, dummy = 0.f;
#pragma unroll
    for (int i = 0; i < 4; i++){ float x = r[t + 128*i]; v[i] = x; s2 += x*x; }
    block_reduce2_128(s2, dummy);
    float inv = 1.0f / fmaxf(sqrtf(s2), 1e-6f);
#pragma unroll
    for (int i = 0; i < 4; i++) r[t + 128*i] = v[i]*inv;
}

// ---------------- pad mask: |text row| sum <= 1e-6 ----------------
__global__ void pad_kernel(const float* __restrict__ text, int* __restrict__ pad){
    int row = blockIdx.x, t = threadIdx.x;
    const float* r = text + (size_t)row * CC;
    float s = 0.f, dummy = 0.f;
#pragma unroll
    for (int i = 0; i < 4; i++) s += fabsf(r[t + 128*i]);
    block_reduce2_128(s, dummy);
    if (t == 0) pad[row] = (s <= 1e-6f) ? 1 : 0;
}

// ---------------- tiled SGEMM: C = A[MxK] @ W[KxN] + bias, opt GELU / residual ----------------
template<bool GELU, bool RES>
__global__ __launch_bounds__(256) void gemm128(
    const float* __restrict__ A, const float* __restrict__ W,
    const float* __restrict__ bias, const float* __restrict__ res,
    float* __restrict__ Cout, int M, int N, int K)
{
    __shared__ float As[8][128];
    __shared__ float Bs[8][128];
    int tid = threadIdx.x;
    int rowBase = blockIdx.y * 128;
    int colBase = blockIdx.x * 128;
    int aRow = tid >> 1;
    int aK4  = (tid & 1) << 2;
    int bRow = tid >> 5;
    int bCol = (tid & 31) << 2;
    int tx = tid & 15, ty = tid >> 4;
    float acc[8][8];
#pragma unroll
    for (int i = 0; i < 8; i++)
#pragma unroll
        for (int j = 0; j < 8; j++) acc[i][j] = 0.f;

    bool aValid = (rowBase + aRow) < M;
    const float* aPtr = A + (size_t)(rowBase + aRow) * K + aK4;
    const float* bPtr = W + (size_t)bRow * N + colBase + bCol;

    for (int k0 = 0; k0 < K; k0 += 8){
        float4 av = aValid ? *(const float4*)(aPtr + k0) : make_float4(0.f,0.f,0.f,0.f);
        As[aK4+0][aRow] = av.x; As[aK4+1][aRow] = av.y;
        As[aK4+2][aRow] = av.z; As[aK4+3][aRow] = av.w;
        *(float4*)&Bs[bRow][bCol] = *(const float4*)(bPtr + (size_t)k0 * N);
        __syncthreads();
#pragma unroll
        for (int kk = 0; kk < 8; kk++){
            float4 m0 = *(const float4*)&As[kk][ty*8];
            float4 m1 = *(const float4*)&As[kk][ty*8+4];
            float4 n0 = *(const float4*)&Bs[kk][tx*8];
            float4 n1 = *(const float4*)&Bs[kk][tx*8+4];
            float rm[8] = {m0.x,m0.y,m0.z,m0.w,m1.x,m1.y,m1.z,m1.w};
            float rn[8] = {n0.x,n0.y,n0.z,n0.w,n1.x,n1.y,n1.z,n1.w};
#pragma unroll
            for (int i = 0; i < 8; i++)
#pragma unroll
                for (int j = 0; j < 8; j++)
                    acc[i][j] = fmaf(rm[i], rn[j], acc[i][j]);
        }
        __syncthreads();
    }

#pragma unroll
    for (int i = 0; i < 8; i++){
        int r = rowBase + ty*8 + i;
        if (r >= M) continue;
#pragma unroll
        for (int j = 0; j < 8; j += 4){
            int c = colBase + tx*8 + j;
            float4 bbv = *(const float4*)&bias[c];
            float4 v = make_float4(acc[i][j]   + bbv.x, acc[i][j+1] + bbv.y,
                                   acc[i][j+2] + bbv.z, acc[i][j+3] + bbv.w);
            if (GELU){
                v.x = gelu_exact(v.x); v.y = gelu_exact(v.y);
                v.z = gelu_exact(v.z); v.w = gelu_exact(v.w);
            }
            if (RES){
                float4 rv = *(const float4*)&res[(size_t)r*N + c];
                v.x += rv.x; v.y += rv.y; v.z += rv.z; v.w += rv.w;
            }
            *(float4*)&Cout[(size_t)r*N + c] = v;
        }
    }
}

// ---------------- fused attention: per (b, h, 32-row chunk) ----------------
// sim -> geo log bias -> pad mask -> top-3 threshold -> softmax -> conf -> attn@V
__global__ __launch_bounds__(256) void attn_kernel(
    const float* __restrict__ qf, const float* __restrict__ kf, const float* __restrict__ vf,
    const float* __restrict__ geo, const int* __restrict__ pad,
    const float* __restrict__ ls_p,
    float* __restrict__ aligned, float* __restrict__ conf_out)
{
    __shared__ float ks[TT*65];
    __shared__ float vs[TT*65];
    __shared__ float qs[32*64];
    __shared__ int   pads[TT];
    const int b = blockIdx.z, h = blockIdx.y;
    const int n0 = blockIdx.x << 5;
    const int tid = threadIdx.x;

    for (int idx = tid; idx < TT*64; idx += 256){
        int t = idx >> 6, d = idx & 63;
        size_t go = ((size_t)(b*TT + t)) * CC + h*DH64 + d;
        ks[t*65+d] = kf[go];
        vs[t*65+d] = vf[go];
    }
    for (int idx = tid; idx < 32*64; idx += 256){
        int r = idx >> 6;
        qs[idx] = qf[((size_t)(b*NSP + n0 + r))*CC + h*DH64 + (idx & 63)];
    }
    if (tid < TT) pads[tid] = pad[b*TT + tid];
    __syncthreads();

    float lsv   = fminf(fmaxf(ls_p[0], -2.0f), 2.0f);
    float scale = expf(lsv) * 0.125f;   // / sqrt(64)
    const int warp = tid >> 5, lane = tid & 31;
    const float NEG = -INFINITY;
    const unsigned FULL = 0xffffffffu;

    for (int rr = 0; rr < 4; rr++){
        int r = (warp << 2) + rr;
        int n = n0 + r;
        float geo_v = fminf(fmaxf(geo[b*NSP + n], 0.3f), 1.0f);
        float logg  = logf(geo_v);

        int  t0 = lane, t1 = lane + 32;
        bool v2 = (lane < 13);
        int  t2 = v2 ? lane + 64 : lane;

        float d0 = 0.f, d1 = 0.f, d2 = 0.f;
#pragma unroll
        for (int dd = 0; dd < 64; dd++){
            float qv = qs[(r << 6) + dd];
            d0 = fmaf(qv, ks[t0*65+dd], d0);
            d1 = fmaf(qv, ks[t1*65+dd], d1);
            d2 = fmaf(qv, ks[t2*65+dd], d2);
        }
        float s0 = pads[t0] ? NEG : fmaf(d0, scale, logg);
        float s1 = pads[t1] ? NEG : fmaf(d1, scale, logg);
        float s2 = (v2 && !pads[t2]) ? fmaf(d2, scale, logg) : NEG;

        // local sort desc of (a,bm,cm)
        float a = s0, bm = s1, cm = s2, tmp;
        if (a < bm){ tmp=a; a=bm; bm=tmp; }
        if (a < cm){ tmp=a; a=cm; cm=tmp; }
        if (bm < cm){ tmp=bm; bm=cm; cm=tmp; }
        // warp butterfly merge of sorted top-3 triples
#pragma unroll
        for (int off = 16; off > 0; off >>= 1){
            float a2 = __shfl_xor_sync(FULL, a,  off);
            float b2 = __shfl_xor_sync(FULL, bm, off);
            float c2 = __shfl_xor_sync(FULL, cm, off);
            float o0, o1, o2;
            if (a >= a2){
                o0 = a;
                if (bm >= a2){ o1 = bm; o2 = fmaxf(cm, a2); }
                else         { o1 = a2; o2 = fmaxf(bm, b2); }
            } else {
                o0 = a2;
                if (b2 >= a){ o1 = b2; o2 = fmaxf(c2, a); }
                else        { o1 = a;  o2 = fmaxf(bm, b2); }
            }
            a = o0; bm = o1; cm = o2;
        }
        float thr = cm, maxv = a;

        float e0 = (s0 >= thr && s0 != NEG) ? expf(s0 - maxv) : 0.f;
        float e1 = (s1 >= thr && s1 != NEG) ? expf(s1 - maxv) : 0.f;
        float e2 = (s2 >= thr && s2 != NEG) ? expf(s2 - maxv) : 0.f;

        float sum = warp_sum(e0 + e1 + e2);
        float cnt = warp_sum((e0 > 0.f ? 1.f : 0.f) + (e1 > 0.f ? 1.f : 0.f) + (e2 > 0.f ? 1.f : 0.f));
        float inv = sum > 0.f ? 1.f / sum : 0.f;
        float a0 = e0*inv, a1 = e1*inv, a2v = e2*inv;

        float mp = warp_max(fmaxf(a0, fmaxf(a1, a2v)));
        float le = 0.f;
        { float p = fmaxf(a0, 1e-8f); le -= p*logf(p); }
        { float p = fmaxf(a1, 1e-8f); le -= p*logf(p); }
        if (v2){ float p = fmaxf(a2v, 1e-8f); le -= p*logf(p); }
        le = warp_sum(le);
        float teff = fmaxf(cnt, 2.0f);
        float ent  = fmaxf(le / logf(teff), 0.f);
        float conf = fminf(fmaxf(mp * (1.f - ent), 0.f), 1.f);
        if (lane == 0) conf_out[((size_t)(b*NSP + n))*HH8 + h] = conf;

        // output: attn @ V (weights broadcast via shuffle)
        float acc0 = 0.f, acc1 = 0.f;
#pragma unroll
        for (int t = 0; t < TT; t++){
            float wgt = __shfl_sync(FULL, (t < 32) ? a0 : ((t < 64) ? a1 : a2v), t & 31);
            acc0 = fmaf(wgt, vs[t*65 + lane],      acc0);
            acc1 = fmaf(wgt, vs[t*65 + 32 + lane], acc1);
        }
        size_t ob = ((size_t)(b*NSP + n))*CC + h*DH64;
        aligned[ob + lane]      = acc0;
        aligned[ob + 32 + lane] = acc1;
    }
}

// ---------------- combine: y = x + alpha*gate*o_scaled; then LN2 -> h ----------------
__global__ void combine_ln2_kernel(
    const float* __restrict__ x, const float* __restrict__ o, const float* __restrict__ g,
    const float* __restrict__ geo, const float* __restrict__ conf,
    const float* __restrict__ alpha_p,
    const float* __restrict__ w, const float* __restrict__ b,
    float* __restrict__ y, float* __restrict__ h)
{
    int row = blockIdx.x, t = threadIdx.x;
    float geo_v = fminf(fmaxf(geo[row], 0.3f), 1.0f);
    const float* cp = conf + (size_t)row*HH8;
    float cf = 0.f;
#pragma unroll
    for (int i = 0; i < 8; i++) cf += cp[i];
    cf *= 0.125f;
    cf = fminf(fmaxf(cf, 0.f), 1.f);
    float cs = 0.35f + 0.65f * cf;
    float al = alpha_p[0];
    size_t base = (size_t)row * CC;

    float vy[4], s = 0.f, s2 = 0.f;
#pragma unroll
    for (int i = 0; i < 4; i++){
        int c = t + 128*i;
        float xv = x[base + c];
        float ov = o[base + c] * cs;
        float gv = geo_v / (1.0f + expf(-g[base + c]));
        float yy = xv + al * gv * ov;
        vy[i] = yy; s += yy; s2 += yy*yy;
    }
    block_reduce2_128(s, s2);
    float mu  = s  * (1.0f/512.0f);
    float var = s2 * (1.0f/512.0f) - mu*mu;
    float rs  = rsqrtf(var + 1e-5f);
#pragma unroll
    for (int i = 0; i < 4; i++){
        int c = t + 128*i;
        y[base + c] = vy[i];
        h[base + c] = (vy[i]-mu)*rs*w[c] + b[c];
    }
}

// ---------------- launch ----------------
extern "C" void kernel_launch(void* const* d_in, const int* in_sizes, int n_in,
                              void* d_out, int out_size)
{
    const float* visual = (const float*)d_in[0];
    const float* text   = (const float*)d_in[1];
    const float* geo    = (const float*)d_in[2];
    const float* ln1w = (const float*)d_in[3];
    const float* ln1b = (const float*)d_in[4];
    const float* wq = (const float*)d_in[5];
    const float* bq = (const float*)d_in[6];
    const float* wk = (const float*)d_in[7];
    const float* bk = (const float*)d_in[8];
    const float* wv = (const float*)d_in[9];
    const float* bv = (const float*)d_in[10];
    const float* wo = (const float*)d_in[11];
    const float* bo = (const float*)d_in[12];
    const float* gate_w = (const float*)d_in[13];
    const float* gate_b = (const float*)d_in[14];
    const float* logit_scale = (const float*)d_in[15];
    const float* alpha = (const float*)d_in[16];
    const float* ln2w = (const float*)d_in[17];
    const float* ln2b = (const float*)d_in[18];
    const float* w1 = (const float*)d_in[19];
    const float* b1 = (const float*)d_in[20];
    const float* w2 = (const float*)d_in[21];
    const float* b2 = (const float*)d_in[22];
    float* out = (float*)d_out;

    float *px, *pq, *pkf, *pvf, *pal, *po, *pg, *pcf, *py, *ph, *pf1;
    int* ppad;
    cudaGetSymbolAddress((void**)&px,  g_x);
    cudaGetSymbolAddress((void**)&pq,  g_q);
    cudaGetSymbolAddress((void**)&pkf, g_kf);
    cudaGetSymbolAddress((void**)&pvf, g_vf);
    cudaGetSymbolAddress((void**)&ppad,g_pad);
    cudaGetSymbolAddress((void**)&pal, g_al);
    cudaGetSymbolAddress((void**)&po,  g_o);
    cudaGetSymbolAddress((void**)&pg,  g_g);
    cudaGetSymbolAddress((void**)&pcf, g_cf);
    cudaGetSymbolAddress((void**)&py,  g_y);
    cudaGetSymbolAddress((void**)&ph,  g_h);
    cudaGetSymbolAddress((void**)&pf1, g_f1);

    // 1) x = LN1(visual)
    ln_kernel<<<MR, 128>>>(visual, ln1w, ln1b, px);
    // 2) q = x@wq + bq ; L2-normalize rows
    gemm128<false,false><<<dim3(4,256), 256>>>(px, wq, bq, nullptr, pq, MR, CC, CC);
    l2norm_kernel<<<MR, 128>>>(pq);
    // 3) k = text@wk + bk (L2-normed); v = text@wv + bv
    gemm128<false,false><<<dim3(4,5), 256>>>(text, wk, bk, nullptr, pkf, MT, CC, CC);
    l2norm_kernel<<<MT, 128>>>(pkf);
    gemm128<false,false><<<dim3(4,5), 256>>>(text, wv, bv, nullptr, pvf, MT, CC, CC);
    // 4) pad mask
    pad_kernel<<<MT, 128>>>(text, ppad);
    // 5) fused attention (sim, top-3, softmax, conf, attn@V)
    attn_kernel<<<dim3(NSP/32, HH8, BB), 256>>>(pq, pkf, pvf, geo, ppad, logit_scale, pal, pcf);
    // 6) o = aligned@wo + bo ; gate = x@gate_w + gate_b
    gemm128<false,false><<<dim3(4,256), 256>>>(pal, wo, bo, nullptr, po, MR, CC, CC);
    gemm128<false,false><<<dim3(4,256), 256>>>(px, gate_w, gate_b, nullptr, pg, MR, CC, CC);
    // 7) y = x + alpha*gate*(o*conf_scale) ; h = LN2(y)
    combine_ln2_kernel<<<MR, 128>>>(px, po, pg, geo, pcf, alpha, ln2w, ln2b, py, ph);
    // 8) ffn
    gemm128<true,false><<<dim3(16,256), 256>>>(ph, w1, b1, nullptr, pf1, MR, FFN, CC);
    gemm128<false,true><<<dim3(4,256), 256>>>(pf1, w2, b2, py, out, MR, CC, FFN);
}

// round 14
// speedup vs baseline: 1.0003x; 1.0003x over previous
#include <cuda_runtime.h>
#include <cuda_bf16.h>
#include <math.h>

// ---------------- problem constants ----------------
#define BB   8
#define HSZ  64
#define WSZ  64
#define NSP  (HSZ*WSZ)          // 4096 spatial positions per batch
#define MR   (BB*NSP)           // 32768 rows
#define CC   512
#define TT   77
#define MT   (BB*TT)            // 616 text rows
#define HH8  8
#define DH64 64
#define FFN  2048

// ---------------- scratch (device globals; no runtime alloc) ----------------
__device__ float g_x  [(size_t)MR*CC];   // LN1 output
__device__ float g_q  [(size_t)MR*CC];   // q projection (l2-normed in place)
__device__ float g_kf [(size_t)MT*CC];
__device__ float g_vf [(size_t)MT*CC];
__device__ int   g_pad[MT];
__device__ float g_al [(size_t)MR*CC];   // attention output (pre-wo)
__device__ float g_o  [(size_t)MR*CC];   // aligned@wo + bo
__device__ float g_g  [(size_t)MR*CC];   // gate linear
__device__ float g_cf [(size_t)MR*HH8];  // per-head conf
__device__ float g_y  [(size_t)MR*CC];   // residual stream
__device__ float g_h  [(size_t)MR*CC];   // LN2 output
__device__ float g_f1 [(size_t)MR*FFN];  // ffn intermediate

// ---------------- helpers ----------------
__device__ __forceinline__ float warp_sum(float v){
#pragma unroll
    for (int o = 16; o > 0; o >>= 1) v += __shfl_xor_sync(0xffffffffu, v, o);
    return v;
}
__device__ __forceinline__ float warp_max(float v){
#pragma unroll
    for (int o = 16; o > 0; o >>= 1) v = fmaxf(v, __shfl_xor_sync(0xffffffffu, v, o));
    return v;
}
__device__ __forceinline__ float gelu_exact(float x){
    return 0.5f * x * (1.0f + erff(x * 0.70710678118654752440f));
}

// block of 128 threads: reduce two partial sums to totals (all threads get result)
__device__ __forceinline__ void block_reduce2_128(float& s, float& s2){
    __shared__ float sh[8];
    s  = warp_sum(s);
    s2 = warp_sum(s2);
    int t = threadIdx.x;
    if ((t & 31) == 0){ sh[t >> 5] = s; sh[4 + (t >> 5)] = s2; }
    __syncthreads();
    s  = sh[0] + sh[1] + sh[2] + sh[3];
    s2 = sh[4] + sh[5] + sh[6] + sh[7];
}

// ---------------- LayerNorm over 512 (one block per row, 128 threads) ----------------
__global__ void ln_kernel(const float* __restrict__ in, const float* __restrict__ w,
                          const float* __restrict__ b, float* __restrict__ out){
    int row = blockIdx.x, t = threadIdx.x;
    const float* p = in + (size_t)row * CC;
    float v[4], s = 0.f, s2 = 0.f;
#pragma unroll
    for (int i = 0; i < 4; i++){ float x = p[t + 128*i]; v[i] = x; s += x; s2 += x*x; }
    block_reduce2_128(s, s2);
    float mu  = s  * (1.0f/512.0f);
    float var = s2 * (1.0f/512.0f) - mu*mu;
    float rs  = rsqrtf(var + 1e-5f);
#pragma unroll
    for (int i = 0; i < 4; i++){
        int c = t + 128*i;
        out[(size_t)row*CC + c] = (v[i]-mu)*rs*w[c] + b[c];
    }
}

// ---------------- row-wise L2 normalize (in place) ----------------
__global__ void l2norm_kernel(float* __restrict__ p){
    int row = blockIdx.x, t = threadIdx.x;
    float* r = p + (size_t)row * CC;
    float v[4], s2 = 0.f, dummy = 0.f;
#pragma unroll
    for (int i = 0; i < 4; i++){ float x = r[t + 128*i]; v[i] = x; s2 += x*x; }
    block_reduce2_128(s2, dummy);
    float inv = 1.0f / fmaxf(sqrtf(s2), 1e-6f);
#pragma unroll
    for (int i = 0; i < 4; i++) r[t + 128*i] = v[i]*inv;
}

// ---------------- pad mask: |text row| sum <= 1e-6 ----------------
__global__ void pad_kernel(const float* __restrict__ text, int* __restrict__ pad){
    int row = blockIdx.x, t = threadIdx.x;
    const float* r = text + (size_t)row * CC;
    float s = 0.f, dummy = 0.f;
#pragma unroll
    for (int i = 0; i < 4; i++) s += fabsf(r[t + 128*i]);
    block_reduce2_128(s, dummy);
    if (t == 0) pad[row] = (s <= 1e-6f) ? 1 : 0;
}

// ---------------- tiled SGEMM: C = A[MxK] @ W[KxN] + bias, opt GELU / residual ----------------
template<bool GELU, bool RES>
__global__ __launch_bounds__(256) void gemm128(
    const float* __restrict__ A, const float* __restrict__ W,
    const float* __restrict__ bias, const float* __restrict__ res,
    float* __restrict__ Cout, int M, int N, int K)
{
    __shared__ float As[8][128];
    __shared__ float Bs[8][128];
    int tid = threadIdx.x;
    int rowBase = blockIdx.y * 128;
    int colBase = blockIdx.x * 128;
    int aRow = tid >> 1;
    int aK4  = (tid & 1) << 2;
    int bRow = tid >> 5;
    int bCol = (tid & 31) << 2;
    int tx = tid & 15, ty = tid >> 4;
    float acc[8][8];
#pragma unroll
    for (int i = 0; i < 8; i++)
#pragma unroll
        for (int j = 0; j < 8; j++) acc[i][j] = 0.f;

    bool aValid = (rowBase + aRow) < M;
    const float* aPtr = A + (size_t)(rowBase + aRow) * K + aK4;
    const float* bPtr = W + (size_t)bRow * N + colBase + bCol;

    for (int k0 = 0; k0 < K; k0 += 8){
        float4 av = aValid ? *(const float4*)(aPtr + k0) : make_float4(0.f,0.f,0.f,0.f);
        As[aK4+0][aRow] = av.x; As[aK4+1][aRow] = av.y;
        As[aK4+2][aRow] = av.z; As[aK4+3][aRow] = av.w;
        *(float4*)&Bs[bRow][bCol] = *(const float4*)(bPtr + (size_t)k0 * N);
        __syncthreads();
#pragma unroll
        for (int kk = 0; kk < 8; kk++){
            float4 m0 = *(const float4*)&As[kk][ty*8];
            float4 m1 = *(const float4*)&As[kk][ty*8+4];
            float4 n0 = *(const float4*)&Bs[kk][tx*8];
            float4 n1 = *(const float4*)&Bs[kk][tx*8+4];
            float rm[8] = {m0.x,m0.y,m0.z,m0.w,m1.x,m1.y,m1.z,m1.w};
            float rn[8] = {n0.x,n0.y,n0.z,n0.w,n1.x,n1.y,n1.z,n1.w};
#pragma unroll
            for (int i = 0; i < 8; i++)
#pragma unroll
                for (int j = 0; j < 8; j++)
                    acc[i][j] = fmaf(rm[i], rn[j], acc[i][j]);
        }
        __syncthreads();
    }

#pragma unroll
    for (int i = 0; i < 8; i++){
        int r = rowBase + ty*8 + i;
        if (r >= M) continue;
#pragma unroll
        for (int j = 0; j < 8; j += 4){
            int c = colBase + tx*8 + j;
            float4 bbv = *(const float4*)&bias[c];
            float4 v = make_float4(acc[i][j]   + bbv.x, acc[i][j+1] + bbv.y,
                                   acc[i][j+2] + bbv.z, acc[i][j+3] + bbv.w);
            if (GELU){
                v.x = gelu_exact(v.x); v.y = gelu_exact(v.y);
                v.z = gelu_exact(v.z); v.w = gelu_exact(v.w);
            }
            if (RES){
                float4 rv = *(const float4*)&res[(size_t)r*N + c];
                v.x += rv.x; v.y += rv.y; v.z += rv.z; v.w += rv.w;
            }
            *(float4*)&Cout[(size_t)r*N + c] = v;
        }
    }
}

// ---------------- fused attention: per (b, h, 32-row chunk) ----------------
// sim -> geo log bias -> pad mask -> top-3 threshold -> softmax -> conf -> attn@V
__global__ __launch_bounds__(256) void attn_kernel(
    const float* __restrict__ qf, const float* __restrict__ kf, const float* __restrict__ vf,
    const float* __restrict__ geo, const int* __restrict__ pad,
    const float* __restrict__ ls_p,
    float* __restrict__ aligned, float* __restrict__ conf_out)
{
    __shared__ float ks[TT*65];
    __shared__ float vs[TT*65];
    __shared__ float qs[32*64];
    __shared__ int   pads[TT];
    const int b = blockIdx.z, h = blockIdx.y;
    const int n0 = blockIdx.x << 5;
    const int tid = threadIdx.x;

    for (int idx = tid; idx < TT*64; idx += 256){
        int t = idx >> 6, d = idx & 63;
        size_t go = ((size_t)(b*TT + t)) * CC + h*DH64 + d;
        ks[t*65+d] = kf[go];
        vs[t*65+d] = vf[go];
    }
    for (int idx = tid; idx < 32*64; idx += 256){
        int r = idx >> 6;
        qs[idx] = qf[((size_t)(b*NSP + n0 + r))*CC + h*DH64 + (idx & 63)];
    }
    if (tid < TT) pads[tid] = pad[b*TT + tid];
    __syncthreads();

    float lsv   = fminf(fmaxf(ls_p[0], -2.0f), 2.0f);
    float scale = expf(lsv) * 0.125f;   // / sqrt(64)
    const int warp = tid >> 5, lane = tid & 31;
    const float NEG = -INFINITY;
    const unsigned FULL = 0xffffffffu;

    for (int rr = 0; rr < 4; rr++){
        int r = (warp << 2) + rr;
        int n = n0 + r;
        float geo_v = fminf(fmaxf(geo[b*NSP + n], 0.3f), 1.0f);
        float logg  = logf(geo_v);

        int  t0 = lane, t1 = lane + 32;
        bool v2 = (lane < 13);
        int  t2 = v2 ? lane + 64 : lane;

        float d0 = 0.f, d1 = 0.f, d2 = 0.f;
#pragma unroll
        for (int dd = 0; dd < 64; dd++){
            float qv = qs[(r << 6) + dd];
            d0 = fmaf(qv, ks[t0*65+dd], d0);
            d1 = fmaf(qv, ks[t1*65+dd], d1);
            d2 = fmaf(qv, ks[t2*65+dd], d2);
        }
        float s0 = pads[t0] ? NEG : fmaf(d0, scale, logg);
        float s1 = pads[t1] ? NEG : fmaf(d1, scale, logg);
        float s2 = (v2 && !pads[t2]) ? fmaf(d2, scale, logg) : NEG;

        // local sort desc of (a,bm,cm)
        float a = s0, bm = s1, cm = s2, tmp;
        if (a < bm){ tmp=a; a=bm; bm=tmp; }
        if (a < cm){ tmp=a; a=cm; cm=tmp; }
        if (bm < cm){ tmp=bm; bm=cm; cm=tmp; }
        // warp butterfly merge of sorted top-3 triples
#pragma unroll
        for (int off = 16; off > 0; off >>= 1){
            float a2 = __shfl_xor_sync(FULL, a,  off);
            float b2 = __shfl_xor_sync(FULL, bm, off);
            float c2 = __shfl_xor_sync(FULL, cm, off);
            float o0, o1, o2;
            if (a >= a2){
                o0 = a;
                if (bm >= a2){ o1 = bm; o2 = fmaxf(cm, a2); }
                else         { o1 = a2; o2 = fmaxf(bm, b2); }
            } else {
                o0 = a2;
                if (b2 >= a){ o1 = b2; o2 = fmaxf(c2, a); }
                else        { o1 = a;  o2 = fmaxf(bm, b2); }
            }
            a = o0; bm = o1; cm = o2;
        }
        float thr = cm, maxv = a;

        float e0 = (s0 >= thr && s0 != NEG) ? expf(s0 - maxv) : 0.f;
        float e1 = (s1 >= thr && s1 != NEG) ? expf(s1 - maxv) : 0.f;
        float e2 = (s2 >= thr && s2 != NEG) ? expf(s2 - maxv) : 0.f;

        float sum = warp_sum(e0 + e1 + e2);
        float cnt = warp_sum((e0 > 0.f ? 1.f : 0.f) + (e1 > 0.f ? 1.f : 0.f) + (e2 > 0.f ? 1.f : 0.f));
        float inv = sum > 0.f ? 1.f / sum : 0.f;
        float a0 = e0*inv, a1 = e1*inv, a2v = e2*inv;

        float mp = warp_max(fmaxf(a0, fmaxf(a1, a2v)));
        float le = 0.f;
        { float p = fmaxf(a0, 1e-8f); le -= p*logf(p); }
        { float p = fmaxf(a1, 1e-8f); le -= p*logf(p); }
        if (v2){ float p = fmaxf(a2v, 1e-8f); le -= p*logf(p); }
        le = warp_sum(le);
        float teff = fmaxf(cnt, 2.0f);
        float ent  = fmaxf(le / logf(teff), 0.f);
        float conf = fminf(fmaxf(mp * (1.f - ent), 0.f), 1.f);
        if (lane == 0) conf_out[((size_t)(b*NSP + n))*HH8 + h] = conf;

        // output: attn @ V (weights broadcast via shuffle)
        float acc0 = 0.f, acc1 = 0.f;
#pragma unroll
        for (int t = 0; t < TT; t++){
            float wgt = __shfl_sync(FULL, (t < 32) ? a0 : ((t < 64) ? a1 : a2v), t & 31);
            acc0 = fmaf(wgt, vs[t*65 + lane],      acc0);
            acc1 = fmaf(wgt, vs[t*65 + 32 + lane], acc1);
        }
        size_t ob = ((size_t)(b*NSP + n))*CC + h*DH64;
        aligned[ob + lane]      = acc0;
        aligned[ob + 32 + lane] = acc1;
    }
}

// ---------------- combine: y = x + alpha*gate*o_scaled; then LN2 -> h ----------------
__global__ void combine_ln2_kernel(
    const float* __restrict__ x, const float* __restrict__ o, const float* __restrict__ g,
    const float* __restrict__ geo, const float* __restrict__ conf,
    const float* __restrict__ alpha_p,
    const float* __restrict__ w, const float* __restrict__ b,
    float* __restrict__ y, float* __restrict__ h)
{
    int row = blockIdx.x, t = threadIdx.x;
    float geo_v = fminf(fmaxf(geo[row], 0.3f), 1.0f);
    const float* cp = conf + (size_t)row*HH8;
    float cf = 0.f;
#pragma unroll
    for (int i = 0; i < 8; i++) cf += cp[i];
    cf *= 0.125f;
    cf = fminf(fmaxf(cf, 0.f), 1.f);
    float cs = 0.35f + 0.65f * cf;
    float al = alpha_p[0];
    size_t base = (size_t)row * CC;

    float vy[4], s = 0.f, s2 = 0.f;
#pragma unroll
    for (int i = 0; i < 4; i++){
        int c = t + 128*i;
        float xv = x[base + c];
        float ov = o[base + c] * cs;
        float gv = geo_v / (1.0f + expf(-g[base + c]));
        float yy = xv + al * gv * ov;
        vy[i] = yy; s += yy; s2 += yy*yy;
    }
    block_reduce2_128(s, s2);
    float mu  = s  * (1.0f/512.0f);
    float var = s2 * (1.0f/512.0f) - mu*mu;
    float rs  = rsqrtf(var + 1e-5f);
#pragma unroll
    for (int i = 0; i < 4; i++){
        int c = t + 128*i;
        y[base + c] = vy[i];
        h[base + c] = (vy[i]-mu)*rs*w[c] + b[c];
    }
}

// ---------------- launch ----------------
extern "C" void kernel_launch(void* const* d_in, const int* in_sizes, int n_in,
                              void* d_out, int out_size)
{
    const float* visual = (const float*)d_in[0];
    const float* text   = (const float*)d_in[1];
    const float* geo    = (const float*)d_in[2];
    const float* ln1w = (const float*)d_in[3];
    const float* ln1b = (const float*)d_in[4];
    const float* wq = (const float*)d_in[5];
    const float* bq = (const float*)d_in[6];
    const float* wk = (const float*)d_in[7];
    const float* bk = (const float*)d_in[8];
    const float* wv = (const float*)d_in[9];
    const float* bv = (const float*)d_in[10];
    const float* wo = (const float*)d_in[11];
    const float* bo = (const float*)d_in[12];
    const float* gate_w = (const float*)d_in[13];
    const float* gate_b = (const float*)d_in[14];
    const float* logit_scale = (const float*)d_in[15];
    const float* alpha = (const float*)d_in[16];
    const float* ln2w = (const float*)d_in[17];
    const float* ln2b = (const float*)d_in[18];
    const float* w1 = (const float*)d_in[19];
    const float* b1 = (const float*)d_in[20];
    const float* w2 = (const float*)d_in[21];
    const float* b2 = (const float*)d_in[22];
    float* out = (float*)d_out;

    float *px, *pq, *pkf, *pvf, *pal, *po, *pg, *pcf, *py, *ph, *pf1;
    int* ppad;
    cudaGetSymbolAddress((void**)&px,  g_x);
    cudaGetSymbolAddress((void**)&pq,  g_q);
    cudaGetSymbolAddress((void**)&pkf, g_kf);
    cudaGetSymbolAddress((void**)&pvf, g_vf);
    cudaGetSymbolAddress((void**)&ppad,g_pad);
    cudaGetSymbolAddress((void**)&pal, g_al);
    cudaGetSymbolAddress((void**)&po,  g_o);
    cudaGetSymbolAddress((void**)&pg,  g_g);
    cudaGetSymbolAddress((void**)&pcf, g_cf);
    cudaGetSymbolAddress((void**)&py,  g_y);
    cudaGetSymbolAddress((void**)&ph,  g_h);
    cudaGetSymbolAddress((void**)&pf1, g_f1);

    // 1) x = LN1(visual)
    ln_kernel<<<MR, 128>>>(visual, ln1w, ln1b, px);
    // 2) q = x@wq + bq ; L2-normalize rows
    gemm128<false,false><<<dim3(4,256), 256>>>(px, wq, bq, nullptr, pq, MR, CC, CC);
    l2norm_kernel<<<MR, 128>>>(pq);
    // 3) k = text@wk + bk (L2-normed); v = text@wv + bv
    gemm128<false,false><<<dim3(4,5), 256>>>(text, wk, bk, nullptr, pkf, MT, CC, CC);
    l2norm_kernel<<<MT, 128>>>(pkf);
    gemm128<false,false><<<dim3(4,5), 256>>>(text, wv, bv, nullptr, pvf, MT, CC, CC);
    // 4) pad mask
    pad_kernel<<<MT, 128>>>(text, ppad);
    // 5) fused attention (sim, top-3, softmax, conf, attn@V)
    attn_kernel<<<dim3(NSP/32, HH8, BB), 256>>>(pq, pkf, pvf, geo, ppad, logit_scale, pal, pcf);
    // 6) o = aligned@wo + bo ; gate = x@gate_w + gate_b
    gemm128<false,false><<<dim3(4,256), 256>>>(pal, wo, bo, nullptr, po, MR, CC, CC);
    gemm128<false,false><<<dim3(4,256), 256>>>(px, gate_w, gate_b, nullptr, pg, MR, CC, CC);
    // 7) y = x + alpha*gate*(o*conf_scale) ; h = LN2(y)
    combine_ln2_kernel<<<MR, 128>>>(px, po, pg, geo, pcf, alpha, ln2w, ln2b, py, ph);
    // 8) ffn
    gemm128<true,false><<<dim3(16,256), 256>>>(ph, w1, b1, nullptr, pf1, MR, FFN, CC);
    gemm128<false,true><<<dim3(4,256), 256>>>(pf1, w2, b2, py, out, MR, CC, FFN);
}

// round 16
// speedup vs baseline: 2.3689x; 2.3681x over previous
#include <cuda_runtime.h>
#include <cuda_bf16.h>
#include <math.h>
#include <stdint.h>

// ---------------- problem constants ----------------
#define BB   8
#define HSZ  64
#define WSZ  64
#define NSP  (HSZ*WSZ)          // 4096 spatial positions per batch
#define MR   (BB*NSP)           // 32768 rows
#define CC   512
#define TT   77
#define MT   (BB*TT)            // 616 text rows
#define HH8  8
#define DH64 64
#define FFN  2048

// ---------------- scratch (device globals; no runtime alloc) ----------------
__device__ float g_x  [(size_t)MR*CC];   // LN1 output
__device__ float g_q  [(size_t)MR*CC];   // q projection (l2-normed in place)
__device__ float g_kf [(size_t)MT*CC];
__device__ float g_vf [(size_t)MT*CC];
__device__ int   g_pad[MT];
__device__ float g_al [(size_t)MR*CC];   // attention output (pre-wo)
__device__ float g_o  [(size_t)MR*CC];   // aligned@wo + bo
__device__ float g_g  [(size_t)MR*CC];   // gate linear
__device__ float g_cf [(size_t)MR*HH8];  // per-head conf
__device__ float g_y  [(size_t)MR*CC];   // residual stream
__device__ float g_h  [(size_t)MR*CC];   // LN2 output
__device__ float g_f1 [(size_t)MR*FFN];  // ffn intermediate
// transposed weights [N,K] K-major
__device__ float g_wqT[(size_t)CC*CC];
__device__ float g_wkT[(size_t)CC*CC];
__device__ float g_wvT[(size_t)CC*CC];
__device__ float g_woT[(size_t)CC*CC];
__device__ float g_gwT[(size_t)CC*CC];
__device__ float g_w1T[(size_t)FFN*CC];
__device__ float g_w2T[(size_t)CC*FFN];

// ---------------- small PTX helpers (base ISA only; no sm_103a features) ----
__device__ __forceinline__ uint32_t smem_to_u32(const void* p) {
    uint32_t a;
    asm("{ .reg .u64 t; cvta.to.shared.u64 t, %1; cvt.u32.u64 %0, t; }" : "=r"(a) : "l"(p));
    return a;
}
__device__ __forceinline__ float to_tf32(float x){
    uint32_t u; asm("cvt.rna.tf32.f32 %0, %1;" : "=r"(u) : "f"(x));
    return __uint_as_float(u);
}
__device__ __forceinline__ float4 cvt4(float4 v){
    v.x = to_tf32(v.x); v.y = to_tf32(v.y);
    v.z = to_tf32(v.z); v.w = to_tf32(v.w);
    return v;
}
__device__ __forceinline__ void ldsm4(uint32_t* r, uint32_t addr){
    asm volatile("ldmatrix.sync.aligned.m8n8.x4.shared.b16 {%0,%1,%2,%3}, [%4];"
        : "=r"(r[0]), "=r"(r[1]), "=r"(r[2]), "=r"(r[3]) : "r"(addr));
}
__device__ __forceinline__ void mma_tf32(float* d, const uint32_t* a, uint32_t b0, uint32_t b1){
    asm volatile(
        "mma.sync.aligned.m16n8k8.row.col.f32.tf32.tf32.f32 "
        "{%0,%1,%2,%3}, {%4,%5,%6,%7}, {%8,%9}, {%0,%1,%2,%3};"
        : "+f"(d[0]), "+f"(d[1]), "+f"(d[2]), "+f"(d[3])
        : "r"(a[0]), "r"(a[1]), "r"(a[2]), "r"(a[3]), "r"(b0), "r"(b1));
}

// ---------------- generic helpers ----------------
__device__ __forceinline__ float warp_sum(float v){
#pragma unroll
    for (int o = 16; o > 0; o >>= 1) v += __shfl_xor_sync(0xffffffffu, v, o);
    return v;
}
__device__ __forceinline__ float warp_max(float v){
#pragma unroll
    for (int o = 16; o > 0; o >>= 1) v = fmaxf(v, __shfl_xor_sync(0xffffffffu, v, o));
    return v;
}
__device__ __forceinline__ float gelu_exact(float x){
    return 0.5f * x * (1.0f + erff(x * 0.70710678118654752440f));
}
__device__ __forceinline__ void block_reduce2_128(float& s, float& s2){
    __shared__ float sh[8];
    s  = warp_sum(s);
    s2 = warp_sum(s2);
    int t = threadIdx.x;
    if ((t & 31) == 0){ sh[t >> 5] = s; sh[4 + (t >> 5)] = s2; }
    __syncthreads();
    s  = sh[0] + sh[1] + sh[2] + sh[3];
    s2 = sh[4] + sh[5] + sh[6] + sh[7];
}

// ---------------- weight transpose: out[N,K] = in[K,N] ----------------
__global__ void transpose_k(const float* __restrict__ in, float* __restrict__ out,
                            int R, int Ccols){
    __shared__ float tile[32][33];
    int c0 = blockIdx.x*32, r0 = blockIdx.y*32;
    int x = threadIdx.x, y = threadIdx.y;   // 32 x 8
#pragma unroll
    for (int i = 0; i < 32; i += 8){
        int r = r0 + y + i, c = c0 + x;
        tile[y+i][x] = (r < R && c < Ccols) ? in[(size_t)r*Ccols + c] : 0.f;
    }
    __syncthreads();
#pragma unroll
    for (int i = 0; i < 32; i += 8){
        int r = c0 + y + i, c = r0 + x;     // out has shape [Ccols, R]
        if (r < Ccols && c < R) out[(size_t)r*R + c] = tile[x][y+i];
    }
}

// ---------------- LayerNorm over 512 ----------------
__global__ void ln_kernel(const float* __restrict__ in, const float* __restrict__ w,
                          const float* __restrict__ b, float* __restrict__ out){
    int row = blockIdx.x, t = threadIdx.x;
    const float* p = in + (size_t)row * CC;
    float v[4], s = 0.f, s2 = 0.f;
#pragma unroll
    for (int i = 0; i < 4; i++){ float x = p[t + 128*i]; v[i] = x; s += x; s2 += x*x; }
    block_reduce2_128(s, s2);
    float mu  = s  * (1.0f/512.0f);
    float var = s2 * (1.0f/512.0f) - mu*mu;
    float rs  = rsqrtf(var + 1e-5f);
#pragma unroll
    for (int i = 0; i < 4; i++){
        int c = t + 128*i;
        out[(size_t)row*CC + c] = (v[i]-mu)*rs*w[c] + b[c];
    }
}

// ---------------- row-wise L2 normalize (in place) ----------------
__global__ void l2norm_kernel(float* __restrict__ p){
    int row = blockIdx.x, t = threadIdx.x;
    float* r = p + (size_t)row * CC;
    float v[4], s2 = 0.f, dummy = 0.f;
#pragma unroll
    for (int i = 0; i < 4; i++){ float x = r[t + 128*i]; v[i] = x; s2 += x*x; }
    block_reduce2_128(s2, dummy);
    float inv = 1.0f / fmaxf(sqrtf(s2), 1e-6f);
#pragma unroll
    for (int i = 0; i < 4; i++) r[t + 128*i] = v[i]*inv;
}

// ---------------- pad mask ----------------
__global__ void pad_kernel(const float* __restrict__ text, int* __restrict__ pad){
    int row = blockIdx.x, t = threadIdx.x;
    const float* r = text + (size_t)row * CC;
    float s = 0.f, dummy = 0.f;
#pragma unroll
    for (int i = 0; i < 4; i++) s += fabsf(r[t + 128*i]);
    block_reduce2_128(s, dummy);
    if (t == 0) pad[row] = (s <= 1e-6f) ? 1 : 0;
}

// ---------------- tensor-core tf32 GEMM via mma.sync ----------------
// C = A[M,K] @ Bt[N,K]^T + bias (opt GELU / residual). 128x128 tile, BK=32,
// double-buffered 64KB SMEM, 8 warps (2x4), warp tile 64x32, m16n8k8 tf32.
#define GEMM_SMEM 65536
// A buf at {0, 16K}, B buf at {32K, 48K}; rows = 128 bytes, XOR swizzle.

template<bool GELU, bool RES>
__global__ __launch_bounds__(256) void gemm_mma(
    const float* __restrict__ A, const float* __restrict__ Bt,
    const float* __restrict__ bias, const float* __restrict__ res,
    float* __restrict__ Cout, int M, int N, int K)
{
    extern __shared__ char smem[];
    uint32_t sb = smem_to_u32(smem);
    const int tid = threadIdx.x;
    const int lane = tid & 31, wid = tid >> 5;
    const int wm = wid >> 2, wn = wid & 3;       // warp grid 2 x 4
    const int mBase = blockIdx.y * 128;
    const int nBase = blockIdx.x * 128;
    const int nch = K >> 5;

    float acc[4][4][4];
#pragma unroll
    for (int i = 0; i < 4; i++)
#pragma unroll
        for (int j = 0; j < 4; j++)
#pragma unroll
            for (int c = 0; c < 4; c++) acc[i][j][c] = 0.f;

    // ldmatrix per-thread addressing constants
    const int lrow  = lane & 15;        // row within 16-row block
    const int lcofs = lane & 16;        // byte col offset: 0 or 16

    // ---- stage chunk 0 ----
    {
#pragma unroll
        for (int it = 0; it < 4; it++){
            int idx = tid + it*256;            // 0..1023 float4 slots
            int row = idx >> 3, c4 = idx & 7;
            int gr = mBase + row;
            float4 va = (gr < M) ? *(const float4*)(A + (size_t)gr*K + c4*4)
                                 : make_float4(0.f,0.f,0.f,0.f);
            float4 vb = *(const float4*)(Bt + (size_t)(nBase+row)*K + c4*4);
            uint32_t soff = (uint32_t)(row*128 + ((c4*16) ^ ((row&7)<<4)));
            *(float4*)(smem + soff)         = cvt4(va);
            *(float4*)(smem + 32768 + soff) = cvt4(vb);
        }
    }
    __syncthreads();

    for (int j = 0; j < nch; j++){
        const int buf = j & 1;

        // prefetch next chunk into registers
        float4 stA[4], stB[4];
        if (j + 1 < nch){
            const int k0 = (j+1) << 5;
#pragma unroll
            for (int it = 0; it < 4; it++){
                int idx = tid + it*256;
                int row = idx >> 3, c4 = idx & 7;
                int gr = mBase + row;
                stA[it] = (gr < M) ? *(const float4*)(A + (size_t)gr*K + k0 + c4*4)
                                   : make_float4(0.f,0.f,0.f,0.f);
                stB[it] = *(const float4*)(Bt + (size_t)(nBase+row)*K + k0 + c4*4);
            }
        }

        // compute on current buffer
        const uint32_t aB = sb + buf*16384;
        const uint32_t bB = sb + 32768 + buf*16384;
#pragma unroll
        for (int ks = 0; ks < 4; ks++){
            uint32_t af[4][4], bf[2][4];
#pragma unroll
            for (int mt = 0; mt < 4; mt++){
                int row = wm*64 + mt*16 + lrow;
                uint32_t off = (uint32_t)(row*128 + ((ks*32 + lcofs) ^ ((row&7)<<4)));
                ldsm4(af[mt], aB + off);
            }
#pragma unroll
            for (int p = 0; p < 2; p++){
                int row = wn*32 + p*16 + lrow;
                uint32_t off = (uint32_t)(row*128 + ((ks*32 + lcofs) ^ ((row&7)<<4)));
                ldsm4(bf[p], bB + off);
            }
#pragma unroll
            for (int mt = 0; mt < 4; mt++)
#pragma unroll
                for (int nt = 0; nt < 4; nt++)
                    mma_tf32(acc[mt][nt], af[mt], bf[nt>>1][nt&1], bf[nt>>1][2+(nt&1)]);
        }

        if (j + 1 < nch){
            const int nbuf = (j+1) & 1;
#pragma unroll
            for (int it = 0; it < 4; it++){
                int idx = tid + it*256;
                int row = idx >> 3, c4 = idx & 7;
                uint32_t soff = (uint32_t)(nbuf*16384 + row*128 + ((c4*16) ^ ((row&7)<<4)));
                *(float4*)(smem + soff)         = cvt4(stA[it]);
                *(float4*)(smem + 32768 + soff) = cvt4(stB[it]);
            }
            __syncthreads();
        }
    }

    // ---- epilogue: registers -> global ----
    const int g = lane >> 2, tg = lane & 3;
#pragma unroll
    for (int mt = 0; mt < 4; mt++){
        int r0 = mBase + wm*64 + mt*16 + g;
#pragma unroll
        for (int half = 0; half < 2; half++){
            int r = r0 + half*8;
            if (r >= M) continue;
#pragma unroll
            for (int nt = 0; nt < 4; nt++){
                int col = nBase + wn*32 + nt*8 + tg*2;
                float c0 = acc[mt][nt][half*2+0] + bias[col];
                float c1 = acc[mt][nt][half*2+1] + bias[col+1];
                if (GELU){ c0 = gelu_exact(c0); c1 = gelu_exact(c1); }
                if (RES){
                    const float2 rv = *(const float2*)&res[(size_t)r*N + col];
                    c0 += rv.x; c1 += rv.y;
                }
                float2 st; st.x = c0; st.y = c1;
                *(float2*)&Cout[(size_t)r*N + col] = st;
            }
        }
    }
}

// ---------------- fused attention (unchanged, verified) ----------------
__global__ __launch_bounds__(256) void attn_kernel(
    const float* __restrict__ qf, const float* __restrict__ kf, const float* __restrict__ vf,
    const float* __restrict__ geo, const int* __restrict__ pad,
    const float* __restrict__ ls_p,
    float* __restrict__ aligned, float* __restrict__ conf_out)
{
    __shared__ float ks[TT*65];
    __shared__ float vs[TT*65];
    __shared__ float qs[32*64];
    __shared__ int   pads[TT];
    const int b = blockIdx.z, h = blockIdx.y;
    const int n0 = blockIdx.x << 5;
    const int tid = threadIdx.x;

    for (int idx = tid; idx < TT*64; idx += 256){
        int t = idx >> 6, d = idx & 63;
        size_t go = ((size_t)(b*TT + t)) * CC + h*DH64 + d;
        ks[t*65+d] = kf[go];
        vs[t*65+d] = vf[go];
    }
    for (int idx = tid; idx < 32*64; idx += 256){
        int r = idx >> 6;
        qs[idx] = qf[((size_t)(b*NSP + n0 + r))*CC + h*DH64 + (idx & 63)];
    }
    if (tid < TT) pads[tid] = pad[b*TT + tid];
    __syncthreads();

    float lsv   = fminf(fmaxf(ls_p[0], -2.0f), 2.0f);
    float scale = expf(lsv) * 0.125f;
    const int warp = tid >> 5, lane = tid & 31;
    const float NEG = -INFINITY;
    const unsigned FULL = 0xffffffffu;

    for (int rr = 0; rr < 4; rr++){
        int r = (warp << 2) + rr;
        int n = n0 + r;
        float geo_v = fminf(fmaxf(geo[b*NSP + n], 0.3f), 1.0f);
        float logg  = logf(geo_v);

        int  t0 = lane, t1 = lane + 32;
        bool v2 = (lane < 13);
        int  t2 = v2 ? lane + 64 : lane;

        float d0 = 0.f, d1 = 0.f, d2 = 0.f;
#pragma unroll
        for (int dd = 0; dd < 64; dd++){
            float qv = qs[(r << 6) + dd];
            d0 = fmaf(qv, ks[t0*65+dd], d0);
            d1 = fmaf(qv, ks[t1*65+dd], d1);
            d2 = fmaf(qv, ks[t2*65+dd], d2);
        }
        float s0 = pads[t0] ? NEG : fmaf(d0, scale, logg);
        float s1 = pads[t1] ? NEG : fmaf(d1, scale, logg);
        float s2 = (v2 && !pads[t2]) ? fmaf(d2, scale, logg) : NEG;

        float a = s0, bm = s1, cm = s2, tmp;
        if (a < bm){ tmp=a; a=bm; bm=tmp; }
        if (a < cm){ tmp=a; a=cm; cm=tmp; }
        if (bm < cm){ tmp=bm; bm=cm; cm=tmp; }
#pragma unroll
        for (int off = 16; off > 0; off >>= 1){
            float a2 = __shfl_xor_sync(FULL, a,  off);
            float b2 = __shfl_xor_sync(FULL, bm, off);
            float c2 = __shfl_xor_sync(FULL, cm, off);
            float o0, o1, o2;
            if (a >= a2){
                o0 = a;
                if (bm >= a2){ o1 = bm; o2 = fmaxf(cm, a2); }
                else         { o1 = a2; o2 = fmaxf(bm, b2); }
            } else {
                o0 = a2;
                if (b2 >= a){ o1 = b2; o2 = fmaxf(c2, a); }
                else        { o1 = a;  o2 = fmaxf(bm, b2); }
            }
            a = o0; bm = o1; cm = o2;
        }
        float thr = cm, maxv = a;

        float e0 = (s0 >= thr && s0 != NEG) ? expf(s0 - maxv) : 0.f;
        float e1 = (s1 >= thr && s1 != NEG) ? expf(s1 - maxv) : 0.f;
        float e2 = (s2 >= thr && s2 != NEG) ? expf(s2 - maxv) : 0.f;

        float sum = warp_sum(e0 + e1 + e2);
        float cnt = warp_sum((e0 > 0.f ? 1.f : 0.f) + (e1 > 0.f ? 1.f : 0.f) + (e2 > 0.f ? 1.f : 0.f));
        float inv = sum > 0.f ? 1.f / sum : 0.f;
        float a0 = e0*inv, a1 = e1*inv, a2v = e2*inv;

        float mp = warp_max(fmaxf(a0, fmaxf(a1, a2v)));
        float le = 0.f;
        { float p = fmaxf(a0, 1e-8f); le -= p*logf(p); }
        { float p = fmaxf(a1, 1e-8f); le -= p*logf(p); }
        if (v2){ float p = fmaxf(a2v, 1e-8f); le -= p*logf(p); }
        le = warp_sum(le);
        float teff = fmaxf(cnt, 2.0f);
        float ent  = fmaxf(le / logf(teff), 0.f);
        float conf = fminf(fmaxf(mp * (1.f - ent), 0.f), 1.f);
        if (lane == 0) conf_out[((size_t)(b*NSP + n))*HH8 + h] = conf;

        float acc0 = 0.f, acc1 = 0.f;
#pragma unroll
        for (int t = 0; t < TT; t++){
            float wgt = __shfl_sync(FULL, (t < 32) ? a0 : ((t < 64) ? a1 : a2v), t & 31);
            acc0 = fmaf(wgt, vs[t*65 + lane],      acc0);
            acc1 = fmaf(wgt, vs[t*65 + 32 + lane], acc1);
        }
        size_t ob = ((size_t)(b*NSP + n))*CC + h*DH64;
        aligned[ob + lane]      = acc0;
        aligned[ob + 32 + lane] = acc1;
    }
}

// ---------------- combine + LN2 ----------------
__global__ void combine_ln2_kernel(
    const float* __restrict__ x, const float* __restrict__ o, const float* __restrict__ g,
    const float* __restrict__ geo, const float* __restrict__ conf,
    const float* __restrict__ alpha_p,
    const float* __restrict__ w, const float* __restrict__ b,
    float* __restrict__ y, float* __restrict__ h)
{
    int row = blockIdx.x, t = threadIdx.x;
    float geo_v = fminf(fmaxf(geo[row], 0.3f), 1.0f);
    const float* cp = conf + (size_t)row*HH8;
    float cf = 0.f;
#pragma unroll
    for (int i = 0; i < 8; i++) cf += cp[i];
    cf *= 0.125f;
    cf = fminf(fmaxf(cf, 0.f), 1.f);
    float cs = 0.35f + 0.65f * cf;
    float al = alpha_p[0];
    size_t base = (size_t)row * CC;

    float vy[4], s = 0.f, s2 = 0.f;
#pragma unroll
    for (int i = 0; i < 4; i++){
        int c = t + 128*i;
        float xv = x[base + c];
        float ov = o[base + c] * cs;
        float gv = geo_v / (1.0f + expf(-g[base + c]));
        float yy = xv + al * gv * ov;
        vy[i] = yy; s += yy; s2 += yy*yy;
    }
    block_reduce2_128(s, s2);
    float mu  = s  * (1.0f/512.0f);
    float var = s2 * (1.0f/512.0f) - mu*mu;
    float rs  = rsqrtf(var + 1e-5f);
#pragma unroll
    for (int i = 0; i < 4; i++){
        int c = t + 128*i;
        y[base + c] = vy[i];
        h[base + c] = (vy[i]-mu)*rs*w[c] + b[c];
    }
}

// ---------------- launch ----------------
extern "C" void kernel_launch(void* const* d_in, const int* in_sizes, int n_in,
                              void* d_out, int out_size)
{
    const float* visual = (const float*)d_in[0];
    const float* text   = (const float*)d_in[1];
    const float* geo    = (const float*)d_in[2];
    const float* ln1w = (const float*)d_in[3];
    const float* ln1b = (const float*)d_in[4];
    const float* wq = (const float*)d_in[5];
    const float* bq = (const float*)d_in[6];
    const float* wk = (const float*)d_in[7];
    const float* bk = (const float*)d_in[8];
    const float* wv = (const float*)d_in[9];
    const float* bv = (const float*)d_in[10];
    const float* wo = (const float*)d_in[11];
    const float* bo = (const float*)d_in[12];
    const float* gate_w = (const float*)d_in[13];
    const float* gate_b = (const float*)d_in[14];
    const float* logit_scale = (const float*)d_in[15];
    const float* alpha = (const float*)d_in[16];
    const float* ln2w = (const float*)d_in[17];
    const float* ln2b = (const float*)d_in[18];
    const float* w1 = (const float*)d_in[19];
    const float* b1 = (const float*)d_in[20];
    const float* w2 = (const float*)d_in[21];
    const float* b2 = (const float*)d_in[22];
    float* out = (float*)d_out;

    float *px, *pq, *pkf, *pvf, *pal, *po, *pg, *pcf, *py, *ph, *pf1;
    float *pwqT, *pwkT, *pwvT, *pwoT, *pgwT, *pw1T, *pw2T;
    int* ppad;
    cudaGetSymbolAddress((void**)&px,  g_x);
    cudaGetSymbolAddress((void**)&pq,  g_q);
    cudaGetSymbolAddress((void**)&pkf, g_kf);
    cudaGetSymbolAddress((void**)&pvf, g_vf);
    cudaGetSymbolAddress((void**)&ppad,g_pad);
    cudaGetSymbolAddress((void**)&pal, g_al);
    cudaGetSymbolAddress((void**)&po,  g_o);
    cudaGetSymbolAddress((void**)&pg,  g_g);
    cudaGetSymbolAddress((void**)&pcf, g_cf);
    cudaGetSymbolAddress((void**)&py,  g_y);
    cudaGetSymbolAddress((void**)&ph,  g_h);
    cudaGetSymbolAddress((void**)&pf1, g_f1);
    cudaGetSymbolAddress((void**)&pwqT, g_wqT);
    cudaGetSymbolAddress((void**)&pwkT, g_wkT);
    cudaGetSymbolAddress((void**)&pwvT, g_wvT);
    cudaGetSymbolAddress((void**)&pwoT, g_woT);
    cudaGetSymbolAddress((void**)&pgwT, g_gwT);
    cudaGetSymbolAddress((void**)&pw1T, g_w1T);
    cudaGetSymbolAddress((void**)&pw2T, g_w2T);

    // opt-in to 64KB dynamic smem for each gemm instantiation (idempotent)
    cudaFuncSetAttribute((const void*)gemm_mma<false,false>,
                         cudaFuncAttributeMaxDynamicSharedMemorySize, GEMM_SMEM);
    cudaFuncSetAttribute((const void*)gemm_mma<true,false>,
                         cudaFuncAttributeMaxDynamicSharedMemorySize, GEMM_SMEM);
    cudaFuncSetAttribute((const void*)gemm_mma<false,true>,
                         cudaFuncAttributeMaxDynamicSharedMemorySize, GEMM_SMEM);

    // 0) transpose weights to [N,K]
    dim3 tb(32, 8);
    transpose_k<<<dim3(16,16), tb>>>(wq,     pwqT, CC,  CC);
    transpose_k<<<dim3(16,16), tb>>>(wk,     pwkT, CC,  CC);
    transpose_k<<<dim3(16,16), tb>>>(wv,     pwvT, CC,  CC);
    transpose_k<<<dim3(16,16), tb>>>(wo,     pwoT, CC,  CC);
    transpose_k<<<dim3(16,16), tb>>>(gate_w, pgwT, CC,  CC);
    transpose_k<<<dim3(64,16), tb>>>(w1,     pw1T, CC,  FFN);
    transpose_k<<<dim3(16,64), tb>>>(w2,     pw2T, FFN, CC);

    // 1) x = LN1(visual)
    ln_kernel<<<MR, 128>>>(visual, ln1w, ln1b, px);
    // 2) q = x@wq + bq ; L2-normalize rows
    gemm_mma<false,false><<<dim3(4,256), 256, GEMM_SMEM>>>(px, pwqT, bq, nullptr, pq, MR, CC, CC);
    l2norm_kernel<<<MR, 128>>>(pq);
    // 3) k = text@wk + bk (L2-normed); v = text@wv + bv
    gemm_mma<false,false><<<dim3(4,5), 256, GEMM_SMEM>>>(text, pwkT, bk, nullptr, pkf, MT, CC, CC);
    l2norm_kernel<<<MT, 128>>>(pkf);
    gemm_mma<false,false><<<dim3(4,5), 256, GEMM_SMEM>>>(text, pwvT, bv, nullptr, pvf, MT, CC, CC);
    // 4) pad mask
    pad_kernel<<<MT, 128>>>(text, ppad);
    // 5) fused attention
    attn_kernel<<<dim3(NSP/32, HH8, BB), 256>>>(pq, pkf, pvf, geo, ppad, logit_scale, pal, pcf);
    // 6) o = aligned@wo + bo ; gate = x@gate_w + gate_b
    gemm_mma<false,false><<<dim3(4,256), 256, GEMM_SMEM>>>(pal, pwoT, bo, nullptr, po, MR, CC, CC);
    gemm_mma<false,false><<<dim3(4,256), 256, GEMM_SMEM>>>(px, pgwT, gate_b, nullptr, pg, MR, CC, CC);
    // 7) combine + LN2
    combine_ln2_kernel<<<MR, 128>>>(px, po, pg, geo, pcf, alpha, ln2w, ln2b, py, ph);
    // 8) ffn
    gemm_mma<true,false><<<dim3(16,256), 256, GEMM_SMEM>>>(ph, pw1T, b1, nullptr, pf1, MR, FFN, CC);
    gemm_mma<false,true><<<dim3(4,256), 256, GEMM_SMEM>>>(pf1, pw2T, b2, py, out, MR, CC, FFN);
}

// round 17
// speedup vs baseline: 3.3104x; 1.3974x over previous
#include <cuda_runtime.h>
#include <cuda_bf16.h>
#include <cuda_fp16.h>
#include <math.h>
#include <stdint.h>

// ---------------- problem constants ----------------
#define BB   8
#define HSZ  64
#define WSZ  64
#define NSP  (HSZ*WSZ)          // 4096 spatial positions per batch
#define MR   (BB*NSP)           // 32768 rows
#define CC   512
#define TT   77
#define MT   (BB*TT)            // 616 text rows
#define HH8  8
#define DH64 64
#define FFN  2048
#define QGP  1024               // pitch of merged q|gate and k|v buffers

// ---------------- scratch (device globals; no runtime alloc) ----------------
__device__ float g_x   [(size_t)MR*CC];    // LN1 output
__device__ float g_qg  [(size_t)MR*QGP];   // [q | gate-linear]
__device__ float g_kv  [(size_t)MT*QGP];   // [k | v]
__device__ int   g_pad [MT];
__device__ float g_invq[MR];
__device__ float g_invk[MT];
__device__ float g_al  [(size_t)MR*CC];    // attention output (pre-wo)
__device__ float g_o   [(size_t)MR*CC];    // aligned@wo + bo
__device__ float g_cf  [(size_t)MR*HH8];   // per-head conf
__device__ float g_y   [(size_t)MR*CC];    // residual stream
__device__ float g_h   [(size_t)MR*CC];    // LN2 output
__device__ float g_f1  [(size_t)MR*FFN];   // ffn intermediate
// transposed weights [N,K] K-major
__device__ float g_wqgT[(size_t)QGP*CC];   // [wq^T ; gate_w^T]
__device__ float g_wkvT[(size_t)QGP*CC];   // [wk^T ; wv^T]
__device__ float g_woT [(size_t)CC*CC];
__device__ float g_w1T [(size_t)FFN*CC];
__device__ float g_w2T [(size_t)CC*FFN];
__device__ float g_bqg [QGP];
__device__ float g_bkv [QGP];

// ---------------- small PTX helpers (base ISA only) ----------------
__device__ __forceinline__ uint32_t smem_to_u32(const void* p) {
    uint32_t a;
    asm("{ .reg .u64 t; cvta.to.shared.u64 t, %1; cvt.u32.u64 %0, t; }" : "=r"(a) : "l"(p));
    return a;
}
__device__ __forceinline__ void ldsm4(uint32_t* r, uint32_t addr){
    asm volatile("ldmatrix.sync.aligned.m8n8.x4.shared.b16 {%0,%1,%2,%3}, [%4];"
        : "=r"(r[0]), "=r"(r[1]), "=r"(r[2]), "=r"(r[3]) : "r"(addr));
}
__device__ __forceinline__ void mma_fp16(float* d, const uint32_t* a, uint32_t b0, uint32_t b1){
    asm volatile(
        "mma.sync.aligned.m16n8k16.row.col.f32.f16.f16.f32 "
        "{%0,%1,%2,%3}, {%4,%5,%6,%7}, {%8,%9}, {%0,%1,%2,%3};"
        : "+f"(d[0]), "+f"(d[1]), "+f"(d[2]), "+f"(d[3])
        : "r"(a[0]), "r"(a[1]), "r"(a[2]), "r"(a[3]), "r"(b0), "r"(b1));
}
__device__ __forceinline__ uint32_t f2h2(float x, float y){
    __half2 h = __floats2half2_rn(x, y);
    return *reinterpret_cast<uint32_t*>(&h);
}
__device__ __forceinline__ uint4 pack8(float4 a, float4 b){
    uint4 r;
    r.x = f2h2(a.x, a.y); r.y = f2h2(a.z, a.w);
    r.z = f2h2(b.x, b.y); r.w = f2h2(b.z, b.w);
    return r;
}

// ---------------- generic helpers ----------------
__device__ __forceinline__ float warp_sum(float v){
#pragma unroll
    for (int o = 16; o > 0; o >>= 1) v += __shfl_xor_sync(0xffffffffu, v, o);
    return v;
}
__device__ __forceinline__ float warp_max(float v){
#pragma unroll
    for (int o = 16; o > 0; o >>= 1) v = fmaxf(v, __shfl_xor_sync(0xffffffffu, v, o));
    return v;
}
__device__ __forceinline__ float gelu_exact(float x){
    return 0.5f * x * (1.0f + erff(x * 0.70710678118654752440f));
}
__device__ __forceinline__ void block_reduce2_128(float& s, float& s2){
    __shared__ float sh[8];
    s  = warp_sum(s);
    s2 = warp_sum(s2);
    int t = threadIdx.x;
    if ((t & 31) == 0){ sh[t >> 5] = s; sh[4 + (t >> 5)] = s2; }
    __syncthreads();
    s  = sh[0] + sh[1] + sh[2] + sh[3];
    s2 = sh[4] + sh[5] + sh[6] + sh[7];
}

// ---------------- weight transpose: out[N,K] = in[K,N] ----------------
__global__ void transpose_k(const float* __restrict__ in, float* __restrict__ out,
                            int R, int Ccols){
    __shared__ float tile[32][33];
    int c0 = blockIdx.x*32, r0 = blockIdx.y*32;
    int x = threadIdx.x, y = threadIdx.y;   // 32 x 8
#pragma unroll
    for (int i = 0; i < 32; i += 8){
        int r = r0 + y + i, c = c0 + x;
        tile[y+i][x] = (r < R && c < Ccols) ? in[(size_t)r*Ccols + c] : 0.f;
    }
    __syncthreads();
#pragma unroll
    for (int i = 0; i < 32; i += 8){
        int r = c0 + y + i, c = r0 + x;     // out has shape [Ccols, R]
        if (r < Ccols && c < R) out[(size_t)r*R + c] = tile[x][y+i];
    }
}

// ---------------- concat two 512-vectors into one 1024-vector ----------------
__global__ void concat2(const float* __restrict__ a, const float* __restrict__ b,
                        float* __restrict__ o){
    int i = blockIdx.x*256 + threadIdx.x;
    if (i < 512) o[i] = a[i];
    else if (i < 1024) o[i] = b[i - 512];
}

// ---------------- LayerNorm over 512 ----------------
__global__ void ln_kernel(const float* __restrict__ in, const float* __restrict__ w,
                          const float* __restrict__ b, float* __restrict__ out){
    int row = blockIdx.x, t = threadIdx.x;
    const float* p = in + (size_t)row * CC;
    float v[4], s = 0.f, s2 = 0.f;
#pragma unroll
    for (int i = 0; i < 4; i++){ float x = p[t + 128*i]; v[i] = x; s += x; s2 += x*x; }
    block_reduce2_128(s, s2);
    float mu  = s  * (1.0f/512.0f);
    float var = s2 * (1.0f/512.0f) - mu*mu;
    float rs  = rsqrtf(var + 1e-5f);
#pragma unroll
    for (int i = 0; i < 4; i++){
        int c = t + 128*i;
        out[(size_t)row*CC + c] = (v[i]-mu)*rs*w[c] + b[c];
    }
}

// ---------------- row L2-norm reciprocal over first 512 cols of pitched buf --
__global__ void rownorm_kernel(const float* __restrict__ p, int pitch,
                               float* __restrict__ invn){
    int row = blockIdx.x, t = threadIdx.x;
    const float* r = p + (size_t)row * pitch;
    float s2 = 0.f, d = 0.f;
#pragma unroll
    for (int i = 0; i < 4; i++){ float x = r[t + 128*i]; s2 += x*x; }
    block_reduce2_128(s2, d);
    if (t == 0) invn[row] = 1.0f / fmaxf(sqrtf(s2), 1e-6f);
}

// ---------------- pad mask ----------------
__global__ void pad_kernel(const float* __restrict__ text, int* __restrict__ pad){
    int row = blockIdx.x, t = threadIdx.x;
    const float* r = text + (size_t)row * CC;
    float s = 0.f, dummy = 0.f;
#pragma unroll
    for (int i = 0; i < 4; i++) s += fabsf(r[t + 128*i]);
    block_reduce2_128(s, dummy);
    if (t == 0) pad[row] = (s <= 1e-6f) ? 1 : 0;
}

// ---------------- fp16 tensor-core GEMM via mma.sync m16n8k16 ---------------
// C = A[M,K] @ Bt[N,K]^T + bias (opt GELU / residual). 128x128 tile, BK=32,
// fp16 operands (converted at staging), fp32 accum. Double-buffered 32KB SMEM.
// 8 warps (2x4), warp tile 64x32.
#define GEMM_SMEM 32768
// A bufs at {0, 8K}; B bufs at {16K, 24K}. Rows = 32 halves = 64B, XOR swizzle.

template<bool GELU, bool RES>
__global__ __launch_bounds__(256) void gemm_mma(
    const float* __restrict__ A, const float* __restrict__ Bt,
    const float* __restrict__ bias, const float* __restrict__ res,
    float* __restrict__ Cout, int M, int N, int K)
{
    extern __shared__ char smem[];
    uint32_t sb = smem_to_u32(smem);
    const int tid = threadIdx.x;
    const int lane = tid & 31, wid = tid >> 5;
    const int wm = wid >> 2, wn = wid & 3;       // warp grid 2 x 4
    const int mBase = blockIdx.y * 128;
    const int nBase = blockIdx.x * 128;
    const int nch = K >> 5;

    float acc[4][4][4];
#pragma unroll
    for (int i = 0; i < 4; i++)
#pragma unroll
        for (int j = 0; j < 4; j++)
#pragma unroll
            for (int c = 0; c < 4; c++) acc[i][j][c] = 0.f;

    const int sRow = tid >> 2, sC = tid & 3;     // 2 slots/thread: rows sRow, sRow+64
    const float4 FZ = make_float4(0.f,0.f,0.f,0.f);

    // ---- stage chunk 0 ----
#pragma unroll
    for (int it = 0; it < 2; it++){
        int row = sRow + it*64;
        int gr = mBase + row;
        int gk = sC*8;
        float4 fa0 = (gr < M) ? *(const float4*)(A + (size_t)gr*K + gk)     : FZ;
        float4 fa1 = (gr < M) ? *(const float4*)(A + (size_t)gr*K + gk + 4) : FZ;
        float4 fb0 = *(const float4*)(Bt + (size_t)(nBase+row)*K + gk);
        float4 fb1 = *(const float4*)(Bt + (size_t)(nBase+row)*K + gk + 4);
        uint32_t soff = (uint32_t)(row*64 + ((sC ^ (row&3))<<4));
        *(uint4*)(smem + soff)         = pack8(fa0, fa1);
        *(uint4*)(smem + 16384 + soff) = pack8(fb0, fb1);
    }
    __syncthreads();

    for (int j = 0; j < nch; j++){
        const int buf = j & 1;

        // prefetch next chunk (raw floats; packed at store time)
        float4 pfa[4], pfb[4];
        if (j + 1 < nch){
            const int k0 = (j+1) << 5;
#pragma unroll
            for (int it = 0; it < 2; it++){
                int row = sRow + it*64;
                int gr = mBase + row;
                int gk = k0 + sC*8;
                pfa[it*2+0] = (gr < M) ? *(const float4*)(A + (size_t)gr*K + gk)     : FZ;
                pfa[it*2+1] = (gr < M) ? *(const float4*)(A + (size_t)gr*K + gk + 4) : FZ;
                pfb[it*2+0] = *(const float4*)(Bt + (size_t)(nBase+row)*K + gk);
                pfb[it*2+1] = *(const float4*)(Bt + (size_t)(nBase+row)*K + gk + 4);
            }
        }

        // compute on current buffer: 2 k16-steps
        const uint32_t aB = sb + buf*8192;
        const uint32_t bB = sb + 16384 + buf*8192;
#pragma unroll
        for (int ks = 0; ks < 2; ks++){
            uint32_t af[4][4], bf[2][4];
#pragma unroll
            for (int mt = 0; mt < 4; mt++){
                int row = wm*64 + mt*16 + (lane & 15);
                int c16 = ks*2 + (lane >> 4);
                ldsm4(af[mt], aB + (uint32_t)(row*64 + ((c16 ^ (row&3))<<4)));
            }
#pragma unroll
            for (int p = 0; p < 2; p++){
                int row = wn*32 + p*16 + (lane & 7) + ((lane >> 4) & 1)*8;
                int c16 = ks*2 + ((lane >> 3) & 1);
                ldsm4(bf[p], bB + (uint32_t)(row*64 + ((c16 ^ (row&3))<<4)));
            }
#pragma unroll
            for (int mt = 0; mt < 4; mt++)
#pragma unroll
                for (int nt = 0; nt < 4; nt++)
                    mma_fp16(acc[mt][nt], af[mt],
                             bf[nt>>1][(nt&1)*2+0], bf[nt>>1][(nt&1)*2+1]);
        }

        if (j + 1 < nch){
            const int nbuf = (j+1) & 1;
#pragma unroll
            for (int it = 0; it < 2; it++){
                int row = sRow + it*64;
                uint32_t soff = (uint32_t)(nbuf*8192 + row*64 + ((sC ^ (row&3))<<4));
                *(uint4*)(smem + soff)         = pack8(pfa[it*2], pfa[it*2+1]);
                *(uint4*)(smem + 16384 + soff) = pack8(pfb[it*2], pfb[it*2+1]);
            }
            __syncthreads();
        }
    }

    // ---- epilogue ----
    const int g = lane >> 2, tg = lane & 3;
#pragma unroll
    for (int mt = 0; mt < 4; mt++){
        int r0 = mBase + wm*64 + mt*16 + g;
#pragma unroll
        for (int half = 0; half < 2; half++){
            int r = r0 + half*8;
            if (r >= M) continue;
#pragma unroll
            for (int nt = 0; nt < 4; nt++){
                int col = nBase + wn*32 + (nt>>1)*16 + (nt&1)*8 + tg*2;
                float c0 = acc[mt][nt][half*2+0] + bias[col];
                float c1 = acc[mt][nt][half*2+1] + bias[col+1];
                if (GELU){ c0 = gelu_exact(c0); c1 = gelu_exact(c1); }
                if (RES){
                    const float2 rv = *(const float2*)&res[(size_t)r*N + col];
                    c0 += rv.x; c1 += rv.y;
                }
                float2 st; st.x = c0; st.y = c1;
                *(float2*)&Cout[(size_t)r*N + col] = st;
            }
        }
    }
}

// ---------------- fused attention ----------------
// q from merged qg buffer (pitch 1024, cols 0-511); k|v from kv buffer
// (pitch 1024, k cols 0-511, v cols 512-1023). L2-norms applied via invq/invk.
// Sparse attn@V: only top-3 survivors accumulate.
__global__ __launch_bounds__(256) void attn_kernel(
    const float* __restrict__ qf, const float* __restrict__ kv,
    const float* __restrict__ geo, const int* __restrict__ pad,
    const float* __restrict__ ls_p,
    const float* __restrict__ invq, const float* __restrict__ invk,
    float* __restrict__ aligned, float* __restrict__ conf_out)
{
    __shared__ float qs[32*64];
    __shared__ float ks[TT*68];
    __shared__ float vs[TT*64];
    __shared__ unsigned char pads[80];
    const int b = blockIdx.z, h = blockIdx.y;
    const int n0 = blockIdx.x << 5;
    const int tid = threadIdx.x;

    for (int idx = tid; idx < TT*16; idx += 256){
        int t = idx >> 4, d4 = (idx & 15) << 2;
        size_t base = ((size_t)(b*TT + t))*QGP + h*DH64 + d4;
        float4 kvk = *(const float4*)(kv + base);
        float4 vvv = *(const float4*)(kv + base + 512);
        float ik = invk[b*TT + t];
        kvk.x *= ik; kvk.y *= ik; kvk.z *= ik; kvk.w *= ik;
        *(float4*)&ks[t*68 + d4] = kvk;
        *(float4*)&vs[t*64 + d4] = vvv;
    }
    for (int idx = tid; idx < 32*16; idx += 256){
        int r = idx >> 4, d4 = (idx & 15) << 2;
        *(float4*)&qs[r*64 + d4] =
            *(const float4*)(qf + ((size_t)(b*NSP + n0 + r))*QGP + h*DH64 + d4);
    }
    if (tid < TT) pads[tid] = (unsigned char)pad[b*TT + tid];
    __syncthreads();

    float lsv   = fminf(fmaxf(ls_p[0], -2.0f), 2.0f);
    float scale = expf(lsv) * 0.125f;   // / sqrt(64)
    const int warp = tid >> 5, lane = tid & 31;
    const float NEG = -INFINITY;
    const unsigned FULL = 0xffffffffu;

    for (int rr = 0; rr < 4; rr++){
        int r = (warp << 2) + rr;
        int n = n0 + r;
        float geo_v = fminf(fmaxf(geo[b*NSP + n], 0.3f), 1.0f);
        float logg  = logf(geo_v);
        float sscale = scale * invq[(size_t)b*NSP + n];

        int  t0 = lane, t1 = lane + 32;
        bool v2 = (lane < 13);
        int  t2 = v2 ? lane + 64 : lane;

        float d0 = 0.f, d1 = 0.f, d2 = 0.f;
        const float* qrow = &qs[r << 6];
#pragma unroll
        for (int i = 0; i < 16; i++){
            float4 qv  = *(const float4*)&qrow[4*i];
            float4 k0v = *(const float4*)&ks[t0*68 + 4*i];
            float4 k1v = *(const float4*)&ks[t1*68 + 4*i];
            float4 k2v = *(const float4*)&ks[t2*68 + 4*i];
            d0 = fmaf(qv.x,k0v.x, fmaf(qv.y,k0v.y, fmaf(qv.z,k0v.z, fmaf(qv.w,k0v.w, d0))));
            d1 = fmaf(qv.x,k1v.x, fmaf(qv.y,k1v.y, fmaf(qv.z,k1v.z, fmaf(qv.w,k1v.w, d1))));
            d2 = fmaf(qv.x,k2v.x, fmaf(qv.y,k2v.y, fmaf(qv.z,k2v.z, fmaf(qv.w,k2v.w, d2))));
        }
        float s0 = pads[t0] ? NEG : fmaf(d0, sscale, logg);
        float s1 = pads[t1] ? NEG : fmaf(d1, sscale, logg);
        float s2 = (v2 && !pads[t2]) ? fmaf(d2, sscale, logg) : NEG;

        // local sort desc + warp butterfly merge of sorted top-3 triples
        float a = s0, bm = s1, cm = s2, tmp;
        if (a < bm){ tmp=a; a=bm; bm=tmp; }
        if (a < cm){ tmp=a; a=cm; cm=tmp; }
        if (bm < cm){ tmp=bm; bm=cm; cm=tmp; }
#pragma unroll
        for (int off = 16; off > 0; off >>= 1){
            float a2 = __shfl_xor_sync(FULL, a,  off);
            float b2 = __shfl_xor_sync(FULL, bm, off);
            float c2 = __shfl_xor_sync(FULL, cm, off);
            float o0, o1, o2;
            if (a >= a2){
                o0 = a;
                if (bm >= a2){ o1 = bm; o2 = fmaxf(cm, a2); }
                else         { o1 = a2; o2 = fmaxf(bm, b2); }
            } else {
                o0 = a2;
                if (b2 >= a){ o1 = b2; o2 = fmaxf(c2, a); }
                else        { o1 = a;  o2 = fmaxf(bm, b2); }
            }
            a = o0; bm = o1; cm = o2;
        }
        float thr = cm, maxv = a;

        float e0 = (s0 >= thr && s0 != NEG) ? expf(s0 - maxv) : 0.f;
        float e1 = (s1 >= thr && s1 != NEG) ? expf(s1 - maxv) : 0.f;
        float e2 = (s2 >= thr && s2 != NEG) ? expf(s2 - maxv) : 0.f;

        unsigned m0 = __ballot_sync(FULL, e0 > 0.f);
        unsigned m1 = __ballot_sync(FULL, e1 > 0.f);
        unsigned m2 = __ballot_sync(FULL, e2 > 0.f);
        float cnt = (float)(__popc(m0) + __popc(m1) + __popc(m2));

        float sum = warp_sum(e0 + e1 + e2);
        float inv = sum > 0.f ? 1.f / sum : 0.f;
        float a0 = e0*inv, a1 = e1*inv, a2v = e2*inv;

        float mp = warp_max(fmaxf(a0, fmaxf(a1, a2v)));
        float le = 0.f;
        { float p = fmaxf(a0, 1e-8f); le -= p*logf(p); }
        { float p = fmaxf(a1, 1e-8f); le -= p*logf(p); }
        if (v2){ float p = fmaxf(a2v, 1e-8f); le -= p*logf(p); }
        le = warp_sum(le);
        float teff = fmaxf(cnt, 2.0f);
        float ent  = fmaxf(le / logf(teff), 0.f);
        float conf = fminf(fmaxf(mp * (1.f - ent), 0.f), 1.f);
        if (lane == 0) conf_out[((size_t)(b*NSP + n))*HH8 + h] = conf;

        // sparse attn @ V: iterate only surviving (nonzero) weights
        float acc0 = 0.f, acc1 = 0.f;
        unsigned mm = m0;
        while (mm){
            int src = __ffs(mm) - 1; mm &= mm - 1;
            float wgt = __shfl_sync(FULL, a0, src);
            acc0 = fmaf(wgt, vs[src*64 + lane],      acc0);
            acc1 = fmaf(wgt, vs[src*64 + 32 + lane], acc1);
        }
        mm = m1;
        while (mm){
            int src = __ffs(mm) - 1; mm &= mm - 1;
            float wgt = __shfl_sync(FULL, a1, src);
            int t = src + 32;
            acc0 = fmaf(wgt, vs[t*64 + lane],      acc0);
            acc1 = fmaf(wgt, vs[t*64 + 32 + lane], acc1);
        }
        mm = m2;
        while (mm){
            int src = __ffs(mm) - 1; mm &= mm - 1;
            float wgt = __shfl_sync(FULL, a2v, src);
            int t = src + 64;
            acc0 = fmaf(wgt, vs[t*64 + lane],      acc0);
            acc1 = fmaf(wgt, vs[t*64 + 32 + lane], acc1);
        }
        size_t ob = ((size_t)(b*NSP + n))*CC + h*DH64;
        aligned[ob + lane]      = acc0;
        aligned[ob + 32 + lane] = acc1;
    }
}

// ---------------- combine + LN2 ----------------
__global__ void combine_ln2_kernel(
    const float* __restrict__ x, const float* __restrict__ o, const float* __restrict__ qg,
    const float* __restrict__ geo, const float* __restrict__ conf,
    const float* __restrict__ alpha_p,
    const float* __restrict__ w, const float* __restrict__ b,
    float* __restrict__ y, float* __restrict__ h)
{
    int row = blockIdx.x, t = threadIdx.x;
    float geo_v = fminf(fmaxf(geo[row], 0.3f), 1.0f);
    const float* cp = conf + (size_t)row*HH8;
    float cf = 0.f;
#pragma unroll
    for (int i = 0; i < 8; i++) cf += cp[i];
    cf *= 0.125f;
    cf = fminf(fmaxf(cf, 0.f), 1.f);
    float cs = 0.35f + 0.65f * cf;
    float al = alpha_p[0];
    size_t base  = (size_t)row * CC;
    size_t baseg = (size_t)row * QGP + 512;

    float vy[4], s = 0.f, s2 = 0.f;
#pragma unroll
    for (int i = 0; i < 4; i++){
        int c = t + 128*i;
        float xv = x[base + c];
        float ov = o[base + c] * cs;
        float gv = geo_v / (1.0f + expf(-qg[baseg + c]));
        float yy = xv + al * gv * ov;
        vy[i] = yy; s += yy; s2 += yy*yy;
    }
    block_reduce2_128(s, s2);
    float mu  = s  * (1.0f/512.0f);
    float var = s2 * (1.0f/512.0f) - mu*mu;
    float rs  = rsqrtf(var + 1e-5f);
#pragma unroll
    for (int i = 0; i < 4; i++){
        int c = t + 128*i;
        y[base + c] = vy[i];
        h[base + c] = (vy[i]-mu)*rs*w[c] + b[c];
    }
}

// ---------------- launch ----------------
extern "C" void kernel_launch(void* const* d_in, const int* in_sizes, int n_in,
                              void* d_out, int out_size)
{
    const float* visual = (const float*)d_in[0];
    const float* text   = (const float*)d_in[1];
    const float* geo    = (const float*)d_in[2];
    const float* ln1w = (const float*)d_in[3];
    const float* ln1b = (const float*)d_in[4];
    const float* wq = (const float*)d_in[5];
    const float* bq = (const float*)d_in[6];
    const float* wk = (const float*)d_in[7];
    const float* bk = (const float*)d_in[8];
    const float* wv = (const float*)d_in[9];
    const float* bv = (const float*)d_in[10];
    const float* wo = (const float*)d_in[11];
    const float* bo = (const float*)d_in[12];
    const float* gate_w = (const float*)d_in[13];
    const float* gate_b = (const float*)d_in[14];
    const float* logit_scale = (const float*)d_in[15];
    const float* alpha = (const float*)d_in[16];
    const float* ln2w = (const float*)d_in[17];
    const float* ln2b = (const float*)d_in[18];
    const float* w1 = (const float*)d_in[19];
    const float* b1 = (const float*)d_in[20];
    const float* w2 = (const float*)d_in[21];
    const float* b2 = (const float*)d_in[22];
    float* out = (float*)d_out;

    float *px, *pqg, *pkv, *pal, *po, *pcf, *py, *ph, *pf1;
    float *pinvq, *pinvk, *pbqg, *pbkv;
    float *pwqgT, *pwkvT, *pwoT, *pw1T, *pw2T;
    int* ppad;
    cudaGetSymbolAddress((void**)&px,   g_x);
    cudaGetSymbolAddress((void**)&pqg,  g_qg);
    cudaGetSymbolAddress((void**)&pkv,  g_kv);
    cudaGetSymbolAddress((void**)&ppad, g_pad);
    cudaGetSymbolAddress((void**)&pinvq,g_invq);
    cudaGetSymbolAddress((void**)&pinvk,g_invk);
    cudaGetSymbolAddress((void**)&pal,  g_al);
    cudaGetSymbolAddress((void**)&po,   g_o);
    cudaGetSymbolAddress((void**)&pcf,  g_cf);
    cudaGetSymbolAddress((void**)&py,   g_y);
    cudaGetSymbolAddress((void**)&ph,   g_h);
    cudaGetSymbolAddress((void**)&pf1,  g_f1);
    cudaGetSymbolAddress((void**)&pwqgT, g_wqgT);
    cudaGetSymbolAddress((void**)&pwkvT, g_wkvT);
    cudaGetSymbolAddress((void**)&pwoT,  g_woT);
    cudaGetSymbolAddress((void**)&pw1T,  g_w1T);
    cudaGetSymbolAddress((void**)&pw2T,  g_w2T);
    cudaGetSymbolAddress((void**)&pbqg,  g_bqg);
    cudaGetSymbolAddress((void**)&pbkv,  g_bkv);

    // 0) transpose weights to [N,K]; build merged weight/bias blocks
    dim3 tb(32, 8);
    transpose_k<<<dim3(16,16), tb>>>(wq,     pwqgT,            CC,  CC);
    transpose_k<<<dim3(16,16), tb>>>(gate_w, pwqgT + 512*512,  CC,  CC);
    transpose_k<<<dim3(16,16), tb>>>(wk,     pwkvT,            CC,  CC);
    transpose_k<<<dim3(16,16), tb>>>(wv,     pwkvT + 512*512,  CC,  CC);
    transpose_k<<<dim3(16,16), tb>>>(wo,     pwoT,             CC,  CC);
    transpose_k<<<dim3(64,16), tb>>>(w1,     pw1T,             CC,  FFN);
    transpose_k<<<dim3(16,64), tb>>>(w2,     pw2T,             FFN, CC);
    concat2<<<4, 256>>>(bq, gate_b, pbqg);
    concat2<<<4, 256>>>(bk, bv,     pbkv);

    // 1) x = LN1(visual)
    ln_kernel<<<MR, 128>>>(visual, ln1w, ln1b, px);
    // 2) [q | gate] = x @ [wq | gate_w] + [bq | gate_b]; q row norms
    gemm_mma<false,false><<<dim3(8,256), 256, GEMM_SMEM>>>(px, pwqgT, pbqg, nullptr, pqg, MR, QGP, CC);
    rownorm_kernel<<<MR, 128>>>(pqg, QGP, pinvq);
    // 3) [k | v] = text @ [wk | wv] + [bk | bv]; k row norms; pad mask
    gemm_mma<false,false><<<dim3(8,5), 256, GEMM_SMEM>>>(text, pwkvT, pbkv, nullptr, pkv, MT, QGP, CC);
    rownorm_kernel<<<MT, 128>>>(pkv, QGP, pinvk);
    pad_kernel<<<MT, 128>>>(text, ppad);
    // 4) fused attention (sim, top-3, softmax, conf, sparse attn@V)
    attn_kernel<<<dim3(NSP/32, HH8, BB), 256>>>(pqg, pkv, geo, ppad, logit_scale,
                                                pinvq, pinvk, pal, pcf);
    // 5) o = aligned@wo + bo
    gemm_mma<false,false><<<dim3(4,256), 256, GEMM_SMEM>>>(pal, pwoT, bo, nullptr, po, MR, CC, CC);
    // 6) combine + LN2
    combine_ln2_kernel<<<MR, 128>>>(px, po, pqg, geo, pcf, alpha, ln2w, ln2b, py, ph);
    // 7) ffn
    gemm_mma<true,false><<<dim3(16,256), 256, GEMM_SMEM>>>(ph, pw1T, b1, nullptr, pf1, MR, FFN, CC);
    gemm_mma<false,true><<<dim3(4,256), 256, GEMM_SMEM>>>(pf1, pw2T, b2, py, out, MR, CC, FFN);
}